// round 13
// baseline (speedup 1.0000x reference)
#include <cuda_runtime.h>
#include <cuda_bf16.h>
#include <cstdint>

#define DD 128
#define MAXN 50000
#define GG 64

// ---------------- device scratch ----------------
__device__ float g_h[(size_t)MAXN * DD];
__device__ float g_agg[(size_t)MAXN * DD];
__device__ float g_t[(size_t)MAXN * DD];
__device__ float g_sums[GG * DD];
__device__ float g_sq[GG * DD];
__device__ int   g_cnt[GG];
__device__ int   g_is64;
// W in mma B-fragment order: [(ks*8+nbp)*32+lane] -> uint4(b0,b1,b2,b3)
__device__ __align__(16) uint4 g_wfe_hi[2048];   // edge lin hi
__device__ __align__(16) uint4 g_wfe_lo[2048];   // edge lin lo
__device__ __align__(16) uint4 g_wf1_hi[2048];   // node lin1 hi
__device__ __align__(16) uint4 g_wf1_lo[2048];   // node lin1 lo

__device__ __forceinline__ long long ld_idx(const void* p, long long i, int is64) {
    return is64 ? ((const long long*)p)[i] : (long long)((const int*)p)[i];
}
__device__ __forceinline__ float silu_f(float x) { return x / (1.0f + __expf(-x)); }

__device__ __forceinline__ uint32_t smem_u32(const void* p) {
    uint32_t a;
    asm("{ .reg .u64 t; cvta.to.shared.u64 t, %1; cvt.u32.u64 %0, t; }" : "=r"(a) : "l"(p));
    return a;
}
__device__ __forceinline__ void cp_async16(uint32_t saddr, const void* g) {
    asm volatile("cp.async.cg.shared.global [%0], [%1], 16;"
                 :: "r"(saddr), "l"(g) : "memory");
}
__device__ __forceinline__ void cp_commit_wait() {
    asm volatile("cp.async.commit_group;" ::: "memory");
    asm volatile("cp.async.wait_group 0;" ::: "memory");
}
__device__ __forceinline__ void mma_bf16(float* d, const uint32_t* a,
                                         uint32_t b0, uint32_t b1) {
    asm volatile("mma.sync.aligned.m16n8k16.row.col.f32.bf16.bf16.f32 "
                 "{%0,%1,%2,%3}, {%4,%5,%6,%7}, {%8,%9}, {%0,%1,%2,%3};"
                 : "+f"(d[0]), "+f"(d[1]), "+f"(d[2]), "+f"(d[3])
                 : "r"(a[0]), "r"(a[1]), "r"(a[2]), "r"(a[3]), "r"(b0), "r"(b1));
}
__device__ __forceinline__ uint32_t pack_bf16x2(float x, float y) {
    __nv_bfloat16 bx = __float2bfloat16(x), by = __float2bfloat16(y);
    return (uint32_t)__bfloat16_as_ushort(bx) | ((uint32_t)__bfloat16_as_ushort(by) << 16);
}
__device__ __forceinline__ uint32_t pack_hi2(float x, float y) {
    return pack_bf16x2(x, y);
}
__device__ __forceinline__ uint32_t pack_lo2(float x, float y) {
    float hx = __bfloat162float(__float2bfloat16(x));
    float hy = __bfloat162float(__float2bfloat16(y));
    return pack_bf16x2(x - hx, y - hy);
}

// ---------------- misc kernels ----------------
__global__ void k_detect(const unsigned* __restrict__ ei) {
    int all0 = 1;
    for (int i = 0; i < 64; i++) all0 &= (ei[2 * i + 1] == 0u);
    g_is64 = all0;
}

__global__ void k_zero(int Nn) {
    long long i = (long long)blockIdx.x * blockDim.x + threadIdx.x;
    long long step = (long long)gridDim.x * blockDim.x;
    long long tot = (long long)Nn * DD;
    for (long long k = i; k < tot; k += step) g_agg[k] = 0.f;
    for (long long k = i; k < GG * DD; k += step) { g_sums[k] = 0.f; g_sq[k] = 0.f; }
    if (i < GG) g_cnt[(int)i] = 0;
}

// Build W fragments from the mma.sync B-fragment mapping:
// frag fi = ks*8+nbp, lane L:
//   b0 = W[n0  ][k0..k0+1]   (n0 = nbp*16 + (L>>2), k0 = ks*16 + 2*(L&3))
//   b1 = W[n0+8][k0..k0+1], b2 = W[n0][k0+8..], b3 = W[n0+8][k0+8..]
__global__ void k_prep_w(const float* __restrict__ We, const float* __restrict__ W1) {
    int tid = blockIdx.x * blockDim.x + threadIdx.x;   // 0..2047
    if (tid >= 2048) return;
    int fi = tid >> 5, lane = tid & 31;
    int ks = fi >> 3, nbp = fi & 7;
    int n0 = nbp * 16 + (lane >> 2);
    int k0 = ks * 16 + 2 * (lane & 3);
    {
        float2 w00 = *(const float2*)(We + n0 * DD + k0);
        float2 w10 = *(const float2*)(We + (n0 + 8) * DD + k0);
        float2 w01 = *(const float2*)(We + n0 * DD + k0 + 8);
        float2 w11 = *(const float2*)(We + (n0 + 8) * DD + k0 + 8);
        g_wfe_hi[tid] = make_uint4(pack_hi2(w00.x, w00.y), pack_hi2(w10.x, w10.y),
                                   pack_hi2(w01.x, w01.y), pack_hi2(w11.x, w11.y));
        g_wfe_lo[tid] = make_uint4(pack_lo2(w00.x, w00.y), pack_lo2(w10.x, w10.y),
                                   pack_lo2(w01.x, w01.y), pack_lo2(w11.x, w11.y));
    }
    {
        float2 w00 = *(const float2*)(W1 + n0 * DD + k0);
        float2 w10 = *(const float2*)(W1 + (n0 + 8) * DD + k0);
        float2 w01 = *(const float2*)(W1 + n0 * DD + k0 + 8);
        float2 w11 = *(const float2*)(W1 + (n0 + 8) * DD + k0 + 8);
        g_wf1_hi[tid] = make_uint4(pack_hi2(w00.x, w00.y), pack_hi2(w10.x, w10.y),
                                   pack_hi2(w01.x, w01.y), pack_hi2(w11.x, w11.y));
        g_wf1_lo[tid] = make_uint4(pack_lo2(w00.x, w00.y), pack_lo2(w10.x, w10.y),
                                   pack_lo2(w01.x, w01.y), pack_lo2(w11.x, w11.y));
    }
}

// ---------------- shared mma-tile machinery (64-row CTA tile) ----------------
// Each warp: strip = wid>>1 (16 rows), half = wid&1 (64 cols). acc = 32 regs.
#define ASTRIDE 136          // A-tile floats per row (conflict-limited LDS.64)
#define DSTR 132             // D staging stride in floats
#define SM_TILE_TOTAL (64 * ASTRIDE * 4)   // 34816 B; D stage (64*132*4=33792) fits

// OOB rows clamped (garbage OK: D rows map 1:1 to A rows; epilogue discards).
__device__ __forceinline__ void tile_gemm_stage(char* smem, uint32_t sb,
                                                const float* __restrict__ X,
                                                const uint4* __restrict__ Wfhi,
                                                const uint4* __restrict__ Wflo,
                                                long long r0, long long rows, int tid) {
    int wid = tid >> 5, lane = tid & 31;
    int strip = wid >> 1, half = wid & 1;

    // async fill of raw fp32 A tile: 64 rows x 32 16B-chunks = 2048
#pragma unroll
    for (int i = 0; i < 8; i++) {
        int idx = tid + i * 256;          // 0..2047
        int row = idx >> 5, q = idx & 31;
        uint32_t sa = sb + (uint32_t)(row * ASTRIDE + q * 4) * 4;
        long long gr = r0 + row;
        if (gr >= rows) gr = rows - 1;
        cp_async16(sa, X + gr * DD + q * 4);
    }
    cp_commit_wait();
    __syncthreads();

    const float* As = (const float*)smem;
    float acc[8][4];
#pragma unroll
    for (int i = 0; i < 8; i++)
#pragma unroll
        for (int j = 0; j < 4; j++) acc[i][j] = 0.f;

    int rowA = strip * 16 + (lane >> 2);
    int kcol = 2 * (lane & 3);
    const float* As0 = As + rowA * ASTRIDE;
    const float* As1 = As + (rowA + 8) * ASTRIDE;

#pragma unroll 1
    for (int ks = 0; ks < 8; ks++) {
        int kb = ks * 16 + kcol;
        float2 x0 = *(const float2*)(As0 + kb);
        float2 x1 = *(const float2*)(As1 + kb);
        float2 x2 = *(const float2*)(As0 + kb + 8);
        float2 x3 = *(const float2*)(As1 + kb + 8);
        uint32_t ahi[4] = { pack_hi2(x0.x, x0.y), pack_hi2(x1.x, x1.y),
                            pack_hi2(x2.x, x2.y), pack_hi2(x3.x, x3.y) };
        uint32_t alo[4] = { pack_lo2(x0.x, x0.y), pack_lo2(x1.x, x1.y),
                            pack_lo2(x2.x, x2.y), pack_lo2(x3.x, x3.y) };
        const uint4* wph = Wfhi + ks * 256 + (half * 4) * 32 + lane;
        const uint4* wpl = Wflo + ks * 256 + (half * 4) * 32 + lane;
#pragma unroll
        for (int j = 0; j < 4; j++) {
            uint4 bh = wph[j * 32];
            uint4 bl = wpl[j * 32];
            mma_bf16(acc[2 * j], ahi, bh.x, bh.z);
            mma_bf16(acc[2 * j + 1], ahi, bh.y, bh.w);
            mma_bf16(acc[2 * j], ahi, bl.x, bl.z);
            mma_bf16(acc[2 * j + 1], ahi, bl.y, bl.w);
            mma_bf16(acc[2 * j], alo, bh.x, bh.z);
            mma_bf16(acc[2 * j + 1], alo, bh.y, bh.w);
        }
    }
    __syncthreads();

    // stage D (reuse tile region): warp covers rows strip*16..+15, cols half*64..+63
    float* Ds = (float*)smem;
    {
        int rbr = strip * 16 + (lane >> 2);
        int cb = half * 64 + (lane & 3) * 2;
#pragma unroll
        for (int nb = 0; nb < 8; nb++) {
            *(float2*)&Ds[rbr * DSTR + cb + nb * 8] = make_float2(acc[nb][0], acc[nb][1]);
            *(float2*)&Ds[(rbr + 8) * DSTR + cb + nb * 8] = make_float2(acc[nb][2], acc[nb][3]);
        }
    }
    __syncthreads();
}

// ---------------- node lin1 via mma ----------------
__global__ __launch_bounds__(256, 3) void k_node_mma(const float* __restrict__ X,
                                                     const float* __restrict__ bias,
                                                     int Nn) {
    extern __shared__ char smem[];
    uint32_t sb = smem_u32(smem);
    int tid = threadIdx.x;
    long long r0 = (long long)blockIdx.x * 64;
    tile_gemm_stage(smem, sb, X, g_wf1_hi, g_wf1_lo, r0, Nn, tid);

    float* Ds = (float*)smem;
    int row = tid >> 2, ch = (tid & 3) * 32;
    long long r = r0 + row;
    if (r < Nn) {
        const float* bp = bias + ch;
        float* op = g_h + r * DD + ch;
#pragma unroll
        for (int j = 0; j < 8; j++) {
            float4 dv = *(const float4*)&Ds[row * DSTR + ch + j * 4];
            float4 bb = *(const float4*)(bp + j * 4);
            *(float4*)(op + j * 4) = make_float4(dv.x + bb.x, dv.y + bb.y,
                                                 dv.z + bb.z, dv.w + bb.w);
        }
    }
}

// ---------------- edge kernel via mma + vector atomics ----------------
__global__ __launch_bounds__(256, 3) void k_edge_mma(const float* __restrict__ EA,
                                                     const float* __restrict__ bias,
                                                     const void* __restrict__ ei,
                                                     int Ee) {
    extern __shared__ char smem[];
    uint32_t sb = smem_u32(smem);
    int tid = threadIdx.x;
    long long r0 = (long long)blockIdx.x * 64;

    // hoist edge indices (L2-resident) before tile work
    int row = tid >> 2, ch = (tid & 3) * 32;
    long long e = r0 + row;
    long long s = 0, d = 0;
    int valid = (e < Ee);
    if (valid) {
        int is64 = g_is64;
        s = ld_idx(ei, e, is64);
        d = ld_idx(ei, (long long)Ee + e, is64);
    }

    tile_gemm_stage(smem, sb, EA, g_wfe_hi, g_wfe_lo, r0, Ee, tid);

    float* Ds = (float*)smem;
    if (valid) {
        const float* hp = g_h + s * DD + ch;
        const float* bp = bias + ch;
        float4* ap = (float4*)(g_agg + d * DD + ch);
#pragma unroll
        for (int j = 0; j < 8; j++) {
            float4 dv = *(const float4*)&Ds[row * DSTR + ch + j * 4];
            float4 hv = *(const float4*)(hp + j * 4);
            float4 bb = *(const float4*)(bp + j * 4);
            float4 m;
            m.x = silu_f(dv.x + bb.x + hv.x);
            m.y = silu_f(dv.y + bb.y + hv.y);
            m.z = silu_f(dv.z + bb.z + hv.z);
            m.w = silu_f(dv.w + bb.w + hv.w);
            atomicAdd(ap + j, m);   // 128-bit RED
        }
    }
}

// ---------------- post kernels (GraphNorm) ----------------
__global__ void k_post1(const float* __restrict__ X, const void* __restrict__ batch,
                        const float* __restrict__ epsp, int Nn) {
    int c = threadIdx.x & 127;
    int half = threadIdx.x >> 7;
    long long n0 = (long long)blockIdx.x * 64 + half * 32;
    float ep = 1.0f + epsp[0];
    int is64 = g_is64;
    int curg = -1; float accv = 0.f; int cr = 0;
    for (int q = 0; q < 32; q++) {
        long long n = n0 + q;
        if (n >= Nn) break;
        long long off = n * DD + c;
        float conv = ep * g_h[off] + g_agg[off];
        float t = silu_f(conv) + X[off];
        g_t[off] = t;
        int g = (int)ld_idx(batch, n, is64);
        if (g != curg) {
            if (curg >= 0) {
                atomicAdd(&g_sums[curg * DD + c], accv);
                if (c == 0) atomicAdd(&g_cnt[curg], cr);
            }
            curg = g; accv = t; cr = 1;
        } else { accv += t; cr++; }
    }
    if (curg >= 0) {
        atomicAdd(&g_sums[curg * DD + c], accv);
        if (c == 0) atomicAdd(&g_cnt[curg], cr);
    }
}

__global__ void k_post2(const void* __restrict__ batch, const float* __restrict__ gms,
                        int Nn) {
    int c = threadIdx.x & 127;
    int half = threadIdx.x >> 7;
    long long n0 = (long long)blockIdx.x * 64 + half * 32;
    int is64 = g_is64;
    float msc = gms[c];
    int curg = -1; float mean = 0.f, ssq = 0.f;
    for (int q = 0; q < 32; q++) {
        long long n = n0 + q;
        if (n >= Nn) break;
        int g = (int)ld_idx(batch, n, is64);
        if (g != curg) {
            if (curg >= 0) atomicAdd(&g_sq[curg * DD + c], ssq);
            curg = g; ssq = 0.f;
            float cf = fmaxf((float)g_cnt[g], 1.f);
            mean = g_sums[g * DD + c] / cf;
        }
        long long off = n * DD + c;
        float o = g_t[off] - mean * msc;
        g_h[off] = o;
        ssq += o * o;
    }
    if (curg >= 0) atomicAdd(&g_sq[curg * DD + c], ssq);
}

__global__ void k_post3(const void* __restrict__ batch, const float* __restrict__ gw,
                        const float* __restrict__ gb, float* __restrict__ out, int Nn) {
    long long i = (long long)blockIdx.x * blockDim.x + threadIdx.x;
    long long step = (long long)gridDim.x * blockDim.x;
    long long tot = (long long)Nn * DD;
    int is64 = g_is64;
    for (long long k = i; k < tot; k += step) {
        long long n = k >> 7;
        int c = (int)(k & 127);
        int g = (int)ld_idx(batch, n, is64);
        float cf = fmaxf((float)g_cnt[g], 1.f);
        float stdv = sqrtf(g_sq[g * DD + c] / cf + 1e-5f);
        out[k] = gw[c] * g_h[k] / stdv + gb[c];
    }
}

// ---------------- launcher ----------------
extern "C" void kernel_launch(void* const* d_in, const int* in_sizes, int n_in,
                              void* d_out, int out_size) {
    const float* node_h    = (const float*)d_in[0];
    const float* edge_attr = (const float*)d_in[1];
    const void*  batch     = d_in[2];
    const void*  ei        = d_in[3];
    const float* w1  = (const float*)d_in[4];
    const float* b1  = (const float*)d_in[5];
    const float* we  = (const float*)d_in[6];
    const float* be  = (const float*)d_in[7];
    const float* eps = (const float*)d_in[8];
    const float* gnw = (const float*)d_in[9];
    const float* gnb = (const float*)d_in[10];
    const float* gms = (const float*)d_in[11];

    int Nn = in_sizes[0] / DD;
    int Ee = in_sizes[1] / DD;

    cudaFuncSetAttribute(k_node_mma, cudaFuncAttributeMaxDynamicSharedMemorySize,
                         SM_TILE_TOTAL);
    cudaFuncSetAttribute(k_edge_mma, cudaFuncAttributeMaxDynamicSharedMemorySize,
                         SM_TILE_TOTAL);

    k_detect<<<1, 1>>>((const unsigned*)ei);
    k_zero<<<1024, 256>>>(Nn);
    k_prep_w<<<8, 256>>>(we, w1);
    k_node_mma<<<(Nn + 63) / 64, 256, SM_TILE_TOTAL>>>(node_h, b1, Nn);
    k_edge_mma<<<(Ee + 63) / 64, 256, SM_TILE_TOTAL>>>(edge_attr, be, ei, Ee);
    k_post1<<<(Nn + 63) / 64, 256>>>(node_h, batch, eps, Nn);
    k_post2<<<(Nn + 63) / 64, 256>>>(batch, gms, Nn);
    k_post3<<<2048, 256>>>(batch, gnw, gnb, (float*)d_out, Nn);
}

// round 14
// speedup vs baseline: 1.5895x; 1.5895x over previous
#include <cuda_runtime.h>
#include <cuda_bf16.h>
#include <cstdint>

#define DD 128
#define MAXN 50000
#define GG 64

// ---------------- device scratch ----------------
__device__ float g_h[(size_t)MAXN * DD];
__device__ float g_agg[(size_t)MAXN * DD];
__device__ float g_t[(size_t)MAXN * DD];
__device__ float g_sums[GG * DD];   // S1 = sum t
__device__ float g_sq[GG * DD];     // S2 = sum t^2
__device__ int   g_cnt[GG];
__device__ int   g_is64;
// W in mma B-fragment order: [(ks*8+nbp)*32+lane] -> uint4(b0,b1,b2,b3)
__device__ __align__(16) uint4 g_wfe_hi[2048];
__device__ __align__(16) uint4 g_wfe_lo[2048];
__device__ __align__(16) uint4 g_wf1_hi[2048];
__device__ __align__(16) uint4 g_wf1_lo[2048];

__device__ __forceinline__ long long ld_idx(const void* p, long long i, int is64) {
    return is64 ? ((const long long*)p)[i] : (long long)((const int*)p)[i];
}
__device__ __forceinline__ float silu_f(float x) { return x / (1.0f + __expf(-x)); }

__device__ __forceinline__ uint32_t smem_u32(const void* p) {
    uint32_t a;
    asm("{ .reg .u64 t; cvta.to.shared.u64 t, %1; cvt.u32.u64 %0, t; }" : "=r"(a) : "l"(p));
    return a;
}
__device__ __forceinline__ void cp_async16(uint32_t saddr, const void* g) {
    asm volatile("cp.async.cg.shared.global [%0], [%1], 16;"
                 :: "r"(saddr), "l"(g) : "memory");
}
__device__ __forceinline__ void cp_commit_wait() {
    asm volatile("cp.async.commit_group;" ::: "memory");
    asm volatile("cp.async.wait_group 0;" ::: "memory");
}
__device__ __forceinline__ void mma_bf16(float* d, const uint32_t* a,
                                         uint32_t b0, uint32_t b1) {
    asm volatile("mma.sync.aligned.m16n8k16.row.col.f32.bf16.bf16.f32 "
                 "{%0,%1,%2,%3}, {%4,%5,%6,%7}, {%8,%9}, {%0,%1,%2,%3};"
                 : "+f"(d[0]), "+f"(d[1]), "+f"(d[2]), "+f"(d[3])
                 : "r"(a[0]), "r"(a[1]), "r"(a[2]), "r"(a[3]), "r"(b0), "r"(b1));
}
__device__ __forceinline__ uint32_t pack_bf16x2(float x, float y) {
    __nv_bfloat16 bx = __float2bfloat16(x), by = __float2bfloat16(y);
    return (uint32_t)__bfloat16_as_ushort(bx) | ((uint32_t)__bfloat16_as_ushort(by) << 16);
}
__device__ __forceinline__ uint32_t pack_hi2(float x, float y) {
    return pack_bf16x2(x, y);
}
__device__ __forceinline__ uint32_t pack_lo2(float x, float y) {
    float hx = __bfloat162float(__float2bfloat16(x));
    float hy = __bfloat162float(__float2bfloat16(y));
    return pack_bf16x2(x - hx, y - hy);
}

// ---------------- zero + dtype detect (fused) ----------------
__global__ void k_zero(const unsigned* __restrict__ ei, int Nn) {
    long long i = (long long)blockIdx.x * blockDim.x + threadIdx.x;
    if (blockIdx.x == 0 && threadIdx.x == 0) {
        int all0 = 1;
        for (int q = 0; q < 64; q++) all0 &= (ei[2 * q + 1] == 0u);
        g_is64 = all0;
    }
    long long step = (long long)gridDim.x * blockDim.x;
    long long tot = (long long)Nn * DD;
    for (long long k = i; k < tot; k += step) g_agg[k] = 0.f;
    for (long long k = i; k < GG * DD; k += step) { g_sums[k] = 0.f; g_sq[k] = 0.f; }
    if (i < GG) g_cnt[(int)i] = 0;
}

// Build W fragments from the mma.sync B-fragment mapping.
__global__ void k_prep_w(const float* __restrict__ We, const float* __restrict__ W1) {
    int tid = blockIdx.x * blockDim.x + threadIdx.x;   // 0..2047
    if (tid >= 2048) return;
    int fi = tid >> 5, lane = tid & 31;
    int ks = fi >> 3, nbp = fi & 7;
    int n0 = nbp * 16 + (lane >> 2);
    int k0 = ks * 16 + 2 * (lane & 3);
    {
        float2 w00 = *(const float2*)(We + n0 * DD + k0);
        float2 w10 = *(const float2*)(We + (n0 + 8) * DD + k0);
        float2 w01 = *(const float2*)(We + n0 * DD + k0 + 8);
        float2 w11 = *(const float2*)(We + (n0 + 8) * DD + k0 + 8);
        g_wfe_hi[tid] = make_uint4(pack_hi2(w00.x, w00.y), pack_hi2(w10.x, w10.y),
                                   pack_hi2(w01.x, w01.y), pack_hi2(w11.x, w11.y));
        g_wfe_lo[tid] = make_uint4(pack_lo2(w00.x, w00.y), pack_lo2(w10.x, w10.y),
                                   pack_lo2(w01.x, w01.y), pack_lo2(w11.x, w11.y));
    }
    {
        float2 w00 = *(const float2*)(W1 + n0 * DD + k0);
        float2 w10 = *(const float2*)(W1 + (n0 + 8) * DD + k0);
        float2 w01 = *(const float2*)(W1 + n0 * DD + k0 + 8);
        float2 w11 = *(const float2*)(W1 + (n0 + 8) * DD + k0 + 8);
        g_wf1_hi[tid] = make_uint4(pack_hi2(w00.x, w00.y), pack_hi2(w10.x, w10.y),
                                   pack_hi2(w01.x, w01.y), pack_hi2(w11.x, w11.y));
        g_wf1_lo[tid] = make_uint4(pack_lo2(w00.x, w00.y), pack_lo2(w10.x, w10.y),
                                   pack_lo2(w01.x, w01.y), pack_lo2(w11.x, w11.y));
    }
}

// ---------------- shared mma-tile machinery ----------------
// CTA = 128 threads (4 warps), tile 64 rows x 128 cols.
// Each warp owns 16 rows x 128 cols (A read/converted exactly once) — R11 mapping.
#define ASTRIDE 136
#define DSTR 132
#define SM_TILE_TOTAL (64 * ASTRIDE * 4)   // 34816 B -> 4 CTAs/SM

__device__ __forceinline__ void tile_gemm_stage(char* smem, uint32_t sb,
                                                const float* __restrict__ X,
                                                const uint4* __restrict__ Wfhi,
                                                const uint4* __restrict__ Wflo,
                                                long long r0, long long rows, int tid) {
    int wid = tid >> 5, lane = tid & 31;

    // async fill of raw fp32 A tile: 64 rows x 32 chunks = 2048 / 128 thr = 16 each
#pragma unroll
    for (int i = 0; i < 16; i++) {
        int idx = tid + i * 128;
        int row = idx >> 5, q = idx & 31;
        uint32_t sa = sb + (uint32_t)(row * ASTRIDE + q * 4) * 4;
        long long gr = r0 + row;
        if (gr >= rows) gr = rows - 1;   // clamp: garbage rows discarded by epilogue
        cp_async16(sa, X + gr * DD + q * 4);
    }
    cp_commit_wait();
    __syncthreads();

    const float* As = (const float*)smem;
    float acc[16][4];
#pragma unroll
    for (int i = 0; i < 16; i++)
#pragma unroll
        for (int j = 0; j < 4; j++) acc[i][j] = 0.f;

    int rowA = wid * 16 + (lane >> 2);
    int kcol = 2 * (lane & 3);
    const float* As0 = As + rowA * ASTRIDE;
    const float* As1 = As + (rowA + 8) * ASTRIDE;

#pragma unroll 1
    for (int ks = 0; ks < 8; ks++) {
        int kb = ks * 16 + kcol;
        float2 x0 = *(const float2*)(As0 + kb);
        float2 x1 = *(const float2*)(As1 + kb);
        float2 x2 = *(const float2*)(As0 + kb + 8);
        float2 x3 = *(const float2*)(As1 + kb + 8);
        uint32_t ahi[4] = { pack_hi2(x0.x, x0.y), pack_hi2(x1.x, x1.y),
                            pack_hi2(x2.x, x2.y), pack_hi2(x3.x, x3.y) };
        uint32_t alo[4] = { pack_lo2(x0.x, x0.y), pack_lo2(x1.x, x1.y),
                            pack_lo2(x2.x, x2.y), pack_lo2(x3.x, x3.y) };
        const uint4* wph = Wfhi + ks * 256 + lane;
        const uint4* wpl = Wflo + ks * 256 + lane;
#pragma unroll
        for (int nbp = 0; nbp < 8; nbp++) {
            uint4 bh = wph[nbp * 32];
            uint4 bl = wpl[nbp * 32];
            mma_bf16(acc[2 * nbp], ahi, bh.x, bh.z);
            mma_bf16(acc[2 * nbp + 1], ahi, bh.y, bh.w);
            mma_bf16(acc[2 * nbp], ahi, bl.x, bl.z);
            mma_bf16(acc[2 * nbp + 1], ahi, bl.y, bl.w);
            mma_bf16(acc[2 * nbp], alo, bh.x, bh.z);
            mma_bf16(acc[2 * nbp + 1], alo, bh.y, bh.w);
        }
    }
    __syncthreads();

    // stage D (reuse tile region)
    float* Ds = (float*)smem;
    {
        int rb = wid * 16 + (lane >> 2);
        int cb = (lane & 3) * 2;
#pragma unroll
        for (int nb = 0; nb < 16; nb++) {
            *(float2*)&Ds[rb * DSTR + nb * 8 + cb] = make_float2(acc[nb][0], acc[nb][1]);
            *(float2*)&Ds[(rb + 8) * DSTR + nb * 8 + cb] = make_float2(acc[nb][2], acc[nb][3]);
        }
    }
    __syncthreads();
}

// ---------------- node lin1 via mma ----------------
__global__ __launch_bounds__(128, 4) void k_node_mma(const float* __restrict__ X,
                                                     const float* __restrict__ bias,
                                                     int Nn) {
    extern __shared__ char smem[];
    uint32_t sb = smem_u32(smem);
    int tid = threadIdx.x;
    long long r0 = (long long)blockIdx.x * 64;
    tile_gemm_stage(smem, sb, X, g_wf1_hi, g_wf1_lo, r0, Nn, tid);

    float* Ds = (float*)smem;
    int row = tid >> 1, ch = (tid & 1) * 64;
    long long r = r0 + row;
    if (r < Nn) {
        const float* bp = bias + ch;
        float* op = g_h + r * DD + ch;
#pragma unroll
        for (int j = 0; j < 16; j++) {
            float4 dv = *(const float4*)&Ds[row * DSTR + ch + j * 4];
            float4 bb = *(const float4*)(bp + j * 4);
            *(float4*)(op + j * 4) = make_float4(dv.x + bb.x, dv.y + bb.y,
                                                 dv.z + bb.z, dv.w + bb.w);
        }
    }
}

// ---------------- edge kernel via mma + vector atomics ----------------
__global__ __launch_bounds__(128, 4) void k_edge_mma(const float* __restrict__ EA,
                                                     const float* __restrict__ bias,
                                                     const void* __restrict__ ei,
                                                     int Ee) {
    extern __shared__ char smem[];
    uint32_t sb = smem_u32(smem);
    int tid = threadIdx.x;
    long long r0 = (long long)blockIdx.x * 64;

    // hoist edge indices before tile work
    int row = tid >> 1, ch = (tid & 1) * 64;
    long long e = r0 + row;
    long long s = 0, d = 0;
    int valid = (e < Ee);
    if (valid) {
        int is64 = g_is64;
        s = ld_idx(ei, e, is64);
        d = ld_idx(ei, (long long)Ee + e, is64);
    }

    tile_gemm_stage(smem, sb, EA, g_wfe_hi, g_wfe_lo, r0, Ee, tid);

    float* Ds = (float*)smem;
    if (valid) {
        const float* hp = g_h + s * DD + ch;
        const float* bp = bias + ch;
        float4* ap = (float4*)(g_agg + d * DD + ch);
#pragma unroll
        for (int j = 0; j < 16; j++) {
            float4 dv = *(const float4*)&Ds[row * DSTR + ch + j * 4];
            float4 hv = *(const float4*)(hp + j * 4);
            float4 bb = *(const float4*)(bp + j * 4);
            float4 m;
            m.x = silu_f(dv.x + bb.x + hv.x);
            m.y = silu_f(dv.y + bb.y + hv.y);
            m.z = silu_f(dv.z + bb.z + hv.z);
            m.w = silu_f(dv.w + bb.w + hv.w);
            atomicAdd(ap + j, m);   // 128-bit RED
        }
    }
}

// ---------------- post kernels (GraphNorm, 2 passes) ----------------
// pass 1: t = silu((1+eps)h + agg) + node_h; accumulate S1, S2, cnt per (g,c)
__global__ void k_post1(const float* __restrict__ X, const void* __restrict__ batch,
                        const float* __restrict__ epsp, int Nn) {
    int c = threadIdx.x & 127;
    int half = threadIdx.x >> 7;
    long long n0 = (long long)blockIdx.x * 64 + half * 32;
    float ep = 1.0f + epsp[0];
    int is64 = g_is64;
    int curg = -1; float s1 = 0.f, s2 = 0.f; int cr = 0;
    for (int q = 0; q < 32; q++) {
        long long n = n0 + q;
        if (n >= Nn) break;
        long long off = n * DD + c;
        float conv = ep * g_h[off] + g_agg[off];
        float t = silu_f(conv) + X[off];
        g_t[off] = t;
        int g = (int)ld_idx(batch, n, is64);
        if (g != curg) {
            if (curg >= 0) {
                atomicAdd(&g_sums[curg * DD + c], s1);
                atomicAdd(&g_sq[curg * DD + c], s2);
                if (c == 0) atomicAdd(&g_cnt[curg], cr);
            }
            curg = g; s1 = t; s2 = t * t; cr = 1;
        } else { s1 += t; s2 += t * t; cr++; }
    }
    if (curg >= 0) {
        atomicAdd(&g_sums[curg * DD + c], s1);
        atomicAdd(&g_sq[curg * DD + c], s2);
        if (c == 0) atomicAdd(&g_cnt[curg], cr);
    }
}

// pass 2: mean = S1/cnt; var = S2/cnt - 2*ms*mean^2 + ms^2*mean^2;
// out = gnw*(t - mean*ms)/sqrt(var+eps) + gnb
__global__ void k_post3(const void* __restrict__ batch, const float* __restrict__ gw,
                        const float* __restrict__ gb, const float* __restrict__ gms,
                        float* __restrict__ out, int Nn) {
    long long i = (long long)blockIdx.x * blockDim.x + threadIdx.x;
    long long step = (long long)gridDim.x * blockDim.x;
    long long tot = (long long)Nn * DD;
    int is64 = g_is64;
    for (long long k = i; k < tot; k += step) {
        long long n = k >> 7;
        int c = (int)(k & 127);
        int g = (int)ld_idx(batch, n, is64);
        float cf = fmaxf((float)g_cnt[g], 1.f);
        float ms = gms[c];
        float mean = g_sums[g * DD + c] / cf;
        float var = g_sq[g * DD + c] / cf + mean * mean * ms * (ms - 2.0f);
        float stdv = sqrtf(var + 1e-5f);
        float o = g_t[k] - mean * ms;
        out[k] = gw[c] * o / stdv + gb[c];
    }
}

// ---------------- launcher ----------------
extern "C" void kernel_launch(void* const* d_in, const int* in_sizes, int n_in,
                              void* d_out, int out_size) {
    const float* node_h    = (const float*)d_in[0];
    const float* edge_attr = (const float*)d_in[1];
    const void*  batch     = d_in[2];
    const void*  ei        = d_in[3];
    const float* w1  = (const float*)d_in[4];
    const float* b1  = (const float*)d_in[5];
    const float* we  = (const float*)d_in[6];
    const float* be  = (const float*)d_in[7];
    const float* eps = (const float*)d_in[8];
    const float* gnw = (const float*)d_in[9];
    const float* gnb = (const float*)d_in[10];
    const float* gms = (const float*)d_in[11];

    int Nn = in_sizes[0] / DD;
    int Ee = in_sizes[1] / DD;

    cudaFuncSetAttribute(k_node_mma, cudaFuncAttributeMaxDynamicSharedMemorySize,
                         SM_TILE_TOTAL);
    cudaFuncSetAttribute(k_edge_mma, cudaFuncAttributeMaxDynamicSharedMemorySize,
                         SM_TILE_TOTAL);

    k_zero<<<1024, 256>>>((const unsigned*)ei, Nn);
    k_prep_w<<<8, 256>>>(we, w1);
    k_node_mma<<<(Nn + 63) / 64, 128, SM_TILE_TOTAL>>>(node_h, b1, Nn);
    k_edge_mma<<<(Ee + 63) / 64, 128, SM_TILE_TOTAL>>>(edge_attr, be, ei, Ee);
    k_post1<<<(Nn + 63) / 64, 256>>>(node_h, batch, eps, Nn);
    k_post3<<<2048, 256>>>(batch, gnw, gnb, gms, (float*)d_out, Nn);
}

// round 15
// speedup vs baseline: 1.6449x; 1.0349x over previous
#include <cuda_runtime.h>
#include <cuda_bf16.h>
#include <cstdint>

#define DD 128
#define MAXN 50000
#define GG 64

// ---------------- device scratch ----------------
__device__ float g_h[(size_t)MAXN * DD];
__device__ float g_agg[(size_t)MAXN * DD];
__device__ float g_t[(size_t)MAXN * DD];
__device__ float g_sums[GG * DD];   // S1 = sum t
__device__ float g_sq[GG * DD];     // S2 = sum t^2
__device__ int   g_cnt[GG];
__device__ int   g_is64;
// W in mma B-fragment order: [(ks*8+nbp)*32+lane] -> uint4(b0,b1,b2,b3)
__device__ __align__(16) uint4 g_wfe_hi[2048];
__device__ __align__(16) uint4 g_wfe_lo[2048];
__device__ __align__(16) uint4 g_wf1_hi[2048];
__device__ __align__(16) uint4 g_wf1_lo[2048];

__device__ __forceinline__ long long ld_idx(const void* p, long long i, int is64) {
    return is64 ? ((const long long*)p)[i] : (long long)((const int*)p)[i];
}
__device__ __forceinline__ float silu_f(float x) { return x / (1.0f + __expf(-x)); }

__device__ __forceinline__ uint32_t smem_u32(const void* p) {
    uint32_t a;
    asm("{ .reg .u64 t; cvta.to.shared.u64 t, %1; cvt.u32.u64 %0, t; }" : "=r"(a) : "l"(p));
    return a;
}
__device__ __forceinline__ void cp_async16(uint32_t saddr, const void* g) {
    asm volatile("cp.async.cg.shared.global [%0], [%1], 16;"
                 :: "r"(saddr), "l"(g) : "memory");
}
__device__ __forceinline__ void cp_commit_wait() {
    asm volatile("cp.async.commit_group;" ::: "memory");
    asm volatile("cp.async.wait_group 0;" ::: "memory");
}
__device__ __forceinline__ void mma_bf16(float* d, const uint32_t* a,
                                         uint32_t b0, uint32_t b1) {
    asm volatile("mma.sync.aligned.m16n8k16.row.col.f32.bf16.bf16.f32 "
                 "{%0,%1,%2,%3}, {%4,%5,%6,%7}, {%8,%9}, {%0,%1,%2,%3};"
                 : "+f"(d[0]), "+f"(d[1]), "+f"(d[2]), "+f"(d[3])
                 : "r"(a[0]), "r"(a[1]), "r"(a[2]), "r"(a[3]), "r"(b0), "r"(b1));
}
__device__ __forceinline__ uint32_t pack_bf16x2(float x, float y) {
    __nv_bfloat16 bx = __float2bfloat16(x), by = __float2bfloat16(y);
    return (uint32_t)__bfloat16_as_ushort(bx) | ((uint32_t)__bfloat16_as_ushort(by) << 16);
}
__device__ __forceinline__ uint32_t pack_hi2(float x, float y) {
    return pack_bf16x2(x, y);
}
__device__ __forceinline__ uint32_t pack_lo2(float x, float y) {
    float hx = __bfloat162float(__float2bfloat16(x));
    float hy = __bfloat162float(__float2bfloat16(y));
    return pack_bf16x2(x - hx, y - hy);
}

// ---------------- zero + dtype detect (fused) ----------------
__global__ void k_zero(const unsigned* __restrict__ ei, int Nn) {
    long long i = (long long)blockIdx.x * blockDim.x + threadIdx.x;
    if (blockIdx.x == 0 && threadIdx.x == 0) {
        int all0 = 1;
        for (int q = 0; q < 64; q++) all0 &= (ei[2 * q + 1] == 0u);
        g_is64 = all0;
    }
    long long step = (long long)gridDim.x * blockDim.x;
    long long tot = (long long)Nn * DD;
    for (long long k = i; k < tot; k += step) g_agg[k] = 0.f;
    for (long long k = i; k < GG * DD; k += step) { g_sums[k] = 0.f; g_sq[k] = 0.f; }
    if (i < GG) g_cnt[(int)i] = 0;
}

// Build W fragments from the mma.sync B-fragment mapping.
__global__ void k_prep_w(const float* __restrict__ We, const float* __restrict__ W1) {
    int tid = blockIdx.x * blockDim.x + threadIdx.x;   // 0..2047
    if (tid >= 2048) return;
    int fi = tid >> 5, lane = tid & 31;
    int ks = fi >> 3, nbp = fi & 7;
    int n0 = nbp * 16 + (lane >> 2);
    int k0 = ks * 16 + 2 * (lane & 3);
    {
        float2 w00 = *(const float2*)(We + n0 * DD + k0);
        float2 w10 = *(const float2*)(We + (n0 + 8) * DD + k0);
        float2 w01 = *(const float2*)(We + n0 * DD + k0 + 8);
        float2 w11 = *(const float2*)(We + (n0 + 8) * DD + k0 + 8);
        g_wfe_hi[tid] = make_uint4(pack_hi2(w00.x, w00.y), pack_hi2(w10.x, w10.y),
                                   pack_hi2(w01.x, w01.y), pack_hi2(w11.x, w11.y));
        g_wfe_lo[tid] = make_uint4(pack_lo2(w00.x, w00.y), pack_lo2(w10.x, w10.y),
                                   pack_lo2(w01.x, w01.y), pack_lo2(w11.x, w11.y));
    }
    {
        float2 w00 = *(const float2*)(W1 + n0 * DD + k0);
        float2 w10 = *(const float2*)(W1 + (n0 + 8) * DD + k0);
        float2 w01 = *(const float2*)(W1 + n0 * DD + k0 + 8);
        float2 w11 = *(const float2*)(W1 + (n0 + 8) * DD + k0 + 8);
        g_wf1_hi[tid] = make_uint4(pack_hi2(w00.x, w00.y), pack_hi2(w10.x, w10.y),
                                   pack_hi2(w01.x, w01.y), pack_hi2(w11.x, w11.y));
        g_wf1_lo[tid] = make_uint4(pack_lo2(w00.x, w00.y), pack_lo2(w10.x, w10.y),
                                   pack_lo2(w01.x, w01.y), pack_lo2(w11.x, w11.y));
    }
}

// ---------------- shared mma-tile machinery ----------------
// CTA = 128 threads (4 warps), tile 64 rows x 128 cols.
// Warp layout: rg = wid>>1 (32 rows), cg = wid&1 (64 cols). acc = 64 regs.
// W traffic per CTA = 2 row-groups x 64KB (halved vs 16-row warps).
#define ASTRIDE 136
#define DSTR 132
#define SM_TILE_TOTAL (64 * ASTRIDE * 4)   // 34816 B -> 4 CTAs/SM

__device__ __forceinline__ void tile_gemm_stage(char* smem, uint32_t sb,
                                                const float* __restrict__ X,
                                                const uint4* __restrict__ Wfhi,
                                                const uint4* __restrict__ Wflo,
                                                long long r0, long long rows, int tid) {
    int wid = tid >> 5, lane = tid & 31;
    int rg = wid >> 1, cg = wid & 1;

    // async fill of raw fp32 A tile: 64 rows x 32 chunks = 2048 / 128 thr = 16 each
#pragma unroll
    for (int i = 0; i < 16; i++) {
        int idx = tid + i * 128;
        int row = idx >> 5, q = idx & 31;
        uint32_t sa = sb + (uint32_t)(row * ASTRIDE + q * 4) * 4;
        long long gr = r0 + row;
        if (gr >= rows) gr = rows - 1;   // clamp: garbage rows discarded by epilogue
        cp_async16(sa, X + gr * DD + q * 4);
    }
    cp_commit_wait();
    __syncthreads();

    const float* As = (const float*)smem;
    float acc[2][8][4];
#pragma unroll
    for (int m = 0; m < 2; m++)
#pragma unroll
        for (int i = 0; i < 8; i++)
#pragma unroll
            for (int j = 0; j < 4; j++) acc[m][i][j] = 0.f;

    int rowA = rg * 32 + (lane >> 2);
    int kcol = 2 * (lane & 3);
    const float* Ap[4];
    Ap[0] = As + rowA * ASTRIDE;
    Ap[1] = As + (rowA + 8) * ASTRIDE;
    Ap[2] = As + (rowA + 16) * ASTRIDE;
    Ap[3] = As + (rowA + 24) * ASTRIDE;

#pragma unroll 1
    for (int ks = 0; ks < 8; ks++) {
        int kb = ks * 16 + kcol;
        uint32_t ahi[2][4], alo[2][4];
#pragma unroll
        for (int m = 0; m < 2; m++) {
            float2 x0 = *(const float2*)(Ap[2 * m] + kb);
            float2 x1 = *(const float2*)(Ap[2 * m + 1] + kb);
            float2 x2 = *(const float2*)(Ap[2 * m] + kb + 8);
            float2 x3 = *(const float2*)(Ap[2 * m + 1] + kb + 8);
            ahi[m][0] = pack_hi2(x0.x, x0.y); ahi[m][1] = pack_hi2(x1.x, x1.y);
            ahi[m][2] = pack_hi2(x2.x, x2.y); ahi[m][3] = pack_hi2(x3.x, x3.y);
            alo[m][0] = pack_lo2(x0.x, x0.y); alo[m][1] = pack_lo2(x1.x, x1.y);
            alo[m][2] = pack_lo2(x2.x, x2.y); alo[m][3] = pack_lo2(x3.x, x3.y);
        }
        const uint4* wph = Wfhi + ks * 256 + (cg * 4) * 32 + lane;
        const uint4* wpl = Wflo + ks * 256 + (cg * 4) * 32 + lane;
#pragma unroll
        for (int j = 0; j < 4; j++) {
            uint4 bh = wph[j * 32];
            uint4 bl = wpl[j * 32];
#pragma unroll
            for (int m = 0; m < 2; m++) {
                mma_bf16(acc[m][2 * j], ahi[m], bh.x, bh.z);
                mma_bf16(acc[m][2 * j + 1], ahi[m], bh.y, bh.w);
                mma_bf16(acc[m][2 * j], ahi[m], bl.x, bl.z);
                mma_bf16(acc[m][2 * j + 1], ahi[m], bl.y, bl.w);
                mma_bf16(acc[m][2 * j], alo[m], bh.x, bh.z);
                mma_bf16(acc[m][2 * j + 1], alo[m], bh.y, bh.w);
            }
        }
    }
    __syncthreads();

    // stage D (reuse tile region): warp covers rows rg*32..+31, cols cg*64..+63
    float* Ds = (float*)smem;
    {
        int cb = cg * 64 + (lane & 3) * 2;
#pragma unroll
        for (int m = 0; m < 2; m++) {
            int rbr = rg * 32 + m * 16 + (lane >> 2);
#pragma unroll
            for (int nb = 0; nb < 8; nb++) {
                *(float2*)&Ds[rbr * DSTR + cb + nb * 8] =
                    make_float2(acc[m][nb][0], acc[m][nb][1]);
                *(float2*)&Ds[(rbr + 8) * DSTR + cb + nb * 8] =
                    make_float2(acc[m][nb][2], acc[m][nb][3]);
            }
        }
    }
    __syncthreads();
}

// ---------------- node lin1 via mma ----------------
__global__ __launch_bounds__(128, 4) void k_node_mma(const float* __restrict__ X,
                                                     const float* __restrict__ bias,
                                                     int Nn) {
    extern __shared__ char smem[];
    uint32_t sb = smem_u32(smem);
    int tid = threadIdx.x;
    long long r0 = (long long)blockIdx.x * 64;
    tile_gemm_stage(smem, sb, X, g_wf1_hi, g_wf1_lo, r0, Nn, tid);

    float* Ds = (float*)smem;
    int row = tid >> 1, ch = (tid & 1) * 64;
    long long r = r0 + row;
    if (r < Nn) {
        const float* bp = bias + ch;
        float* op = g_h + r * DD + ch;
#pragma unroll
        for (int j = 0; j < 16; j++) {
            float4 dv = *(const float4*)&Ds[row * DSTR + ch + j * 4];
            float4 bb = *(const float4*)(bp + j * 4);
            *(float4*)(op + j * 4) = make_float4(dv.x + bb.x, dv.y + bb.y,
                                                 dv.z + bb.z, dv.w + bb.w);
        }
    }
}

// ---------------- edge kernel via mma + vector atomics ----------------
__global__ __launch_bounds__(128, 4) void k_edge_mma(const float* __restrict__ EA,
                                                     const float* __restrict__ bias,
                                                     const void* __restrict__ ei,
                                                     int Ee) {
    extern __shared__ char smem[];
    uint32_t sb = smem_u32(smem);
    int tid = threadIdx.x;
    long long r0 = (long long)blockIdx.x * 64;

    // hoist edge indices before tile work
    int row = tid >> 1, ch = (tid & 1) * 64;
    long long e = r0 + row;
    long long s = 0, d = 0;
    int valid = (e < Ee);
    if (valid) {
        int is64 = g_is64;
        s = ld_idx(ei, e, is64);
        d = ld_idx(ei, (long long)Ee + e, is64);
    }

    tile_gemm_stage(smem, sb, EA, g_wfe_hi, g_wfe_lo, r0, Ee, tid);

    float* Ds = (float*)smem;
    if (valid) {
        const float* hp = g_h + s * DD + ch;
        const float* bp = bias + ch;
        float4* ap = (float4*)(g_agg + d * DD + ch);
#pragma unroll
        for (int j = 0; j < 16; j++) {
            float4 dv = *(const float4*)&Ds[row * DSTR + ch + j * 4];
            float4 hv = *(const float4*)(hp + j * 4);
            float4 bb = *(const float4*)(bp + j * 4);
            float4 m;
            m.x = silu_f(dv.x + bb.x + hv.x);
            m.y = silu_f(dv.y + bb.y + hv.y);
            m.z = silu_f(dv.z + bb.z + hv.z);
            m.w = silu_f(dv.w + bb.w + hv.w);
            atomicAdd(ap + j, m);   // 128-bit RED
        }
    }
}

// ---------------- post kernels (GraphNorm, 2 passes) ----------------
__global__ void k_post1(const float* __restrict__ X, const void* __restrict__ batch,
                        const float* __restrict__ epsp, int Nn) {
    int c = threadIdx.x & 127;
    int half = threadIdx.x >> 7;
    long long n0 = (long long)blockIdx.x * 64 + half * 32;
    float ep = 1.0f + epsp[0];
    int is64 = g_is64;
    int curg = -1; float s1 = 0.f, s2 = 0.f; int cr = 0;
    for (int q = 0; q < 32; q++) {
        long long n = n0 + q;
        if (n >= Nn) break;
        long long off = n * DD + c;
        float conv = ep * g_h[off] + g_agg[off];
        float t = silu_f(conv) + X[off];
        g_t[off] = t;
        int g = (int)ld_idx(batch, n, is64);
        if (g != curg) {
            if (curg >= 0) {
                atomicAdd(&g_sums[curg * DD + c], s1);
                atomicAdd(&g_sq[curg * DD + c], s2);
                if (c == 0) atomicAdd(&g_cnt[curg], cr);
            }
            curg = g; s1 = t; s2 = t * t; cr = 1;
        } else { s1 += t; s2 += t * t; cr++; }
    }
    if (curg >= 0) {
        atomicAdd(&g_sums[curg * DD + c], s1);
        atomicAdd(&g_sq[curg * DD + c], s2);
        if (c == 0) atomicAdd(&g_cnt[curg], cr);
    }
}

__global__ void k_post3(const void* __restrict__ batch, const float* __restrict__ gw,
                        const float* __restrict__ gb, const float* __restrict__ gms,
                        float* __restrict__ out, int Nn) {
    long long i = (long long)blockIdx.x * blockDim.x + threadIdx.x;
    long long step = (long long)gridDim.x * blockDim.x;
    long long tot = (long long)Nn * DD;
    int is64 = g_is64;
    for (long long k = i; k < tot; k += step) {
        long long n = k >> 7;
        int c = (int)(k & 127);
        int g = (int)ld_idx(batch, n, is64);
        float cf = fmaxf((float)g_cnt[g], 1.f);
        float ms = gms[c];
        float mean = g_sums[g * DD + c] / cf;
        float var = g_sq[g * DD + c] / cf + mean * mean * ms * (ms - 2.0f);
        float stdv = sqrtf(var + 1e-5f);
        float o = g_t[k] - mean * ms;
        out[k] = gw[c] * o / stdv + gb[c];
    }
}

// ---------------- launcher ----------------
extern "C" void kernel_launch(void* const* d_in, const int* in_sizes, int n_in,
                              void* d_out, int out_size) {
    const float* node_h    = (const float*)d_in[0];
    const float* edge_attr = (const float*)d_in[1];
    const void*  batch     = d_in[2];
    const void*  ei        = d_in[3];
    const float* w1  = (const float*)d_in[4];
    const float* b1  = (const float*)d_in[5];
    const float* we  = (const float*)d_in[6];
    const float* be  = (const float*)d_in[7];
    const float* eps = (const float*)d_in[8];
    const float* gnw = (const float*)d_in[9];
    const float* gnb = (const float*)d_in[10];
    const float* gms = (const float*)d_in[11];

    int Nn = in_sizes[0] / DD;
    int Ee = in_sizes[1] / DD;

    cudaFuncSetAttribute(k_node_mma, cudaFuncAttributeMaxDynamicSharedMemorySize,
                         SM_TILE_TOTAL);
    cudaFuncSetAttribute(k_edge_mma, cudaFuncAttributeMaxDynamicSharedMemorySize,
                         SM_TILE_TOTAL);

    k_zero<<<1024, 256>>>((const unsigned*)ei, Nn);
    k_prep_w<<<8, 256>>>(we, w1);
    k_node_mma<<<(Nn + 63) / 64, 128, SM_TILE_TOTAL>>>(node_h, b1, Nn);
    k_edge_mma<<<(Ee + 63) / 64, 128, SM_TILE_TOTAL>>>(edge_attr, be, ei, Ee);
    k_post1<<<(Nn + 63) / 64, 256>>>(node_h, batch, eps, Nn);
    k_post3<<<2048, 256>>>(batch, gnw, gnb, gms, (float*)d_out, Nn);
}

// round 17
// speedup vs baseline: 1.7839x; 1.0845x over previous
#include <cuda_runtime.h>
#include <cuda_fp16.h>
#include <cstdint>

#define DD 128
#define MAXN 50000
#define GG 64

// ---------------- device scratch ----------------
__device__ float g_h[(size_t)MAXN * DD];
__device__ float g_agg[(size_t)MAXN * DD];
__device__ float g_t[(size_t)MAXN * DD];
__device__ float g_sums[GG * DD];   // S1 = sum t
__device__ float g_sq[GG * DD];     // S2 = sum t^2
__device__ int   g_cnt[GG];
__device__ int   g_is64;
// W (fp16, single) in mma B-fragment order: [(ks*8+nbp)*32+lane] -> uint4
__device__ __align__(16) uint4 g_wfe[2048];   // edge lin
__device__ __align__(16) uint4 g_wf1[2048];   // node lin1

__device__ __forceinline__ long long ld_idx(const void* p, long long i, int is64) {
    return is64 ? ((const long long*)p)[i] : (long long)((const int*)p)[i];
}
__device__ __forceinline__ float silu_f(float x) { return x / (1.0f + __expf(-x)); }

__device__ __forceinline__ uint32_t smem_u32(const void* p) {
    uint32_t a;
    asm("{ .reg .u64 t; cvta.to.shared.u64 t, %1; cvt.u32.u64 %0, t; }" : "=r"(a) : "l"(p));
    return a;
}
__device__ __forceinline__ void cp_async16(uint32_t saddr, const void* g) {
    asm volatile("cp.async.cg.shared.global [%0], [%1], 16;"
                 :: "r"(saddr), "l"(g) : "memory");
}
__device__ __forceinline__ void cp_commit_wait() {
    asm volatile("cp.async.commit_group;" ::: "memory");
    asm volatile("cp.async.wait_group 0;" ::: "memory");
}
__device__ __forceinline__ void mma_f16(float* d, const uint32_t* a,
                                        uint32_t b0, uint32_t b1) {
    asm volatile("mma.sync.aligned.m16n8k16.row.col.f32.f16.f16.f32 "
                 "{%0,%1,%2,%3}, {%4,%5,%6,%7}, {%8,%9}, {%0,%1,%2,%3};"
                 : "+f"(d[0]), "+f"(d[1]), "+f"(d[2]), "+f"(d[3])
                 : "r"(a[0]), "r"(a[1]), "r"(a[2]), "r"(a[3]), "r"(b0), "r"(b1));
}
__device__ __forceinline__ uint32_t pack_h2(float x, float y) {
    __half2 h = __floats2half2_rn(x, y);
    return *(uint32_t*)&h;
}
__device__ __forceinline__ uint32_t pack_h2_lo(float x, float y) {
    float hx = __half2float(__float2half_rn(x));
    float hy = __half2float(__float2half_rn(y));
    return pack_h2(x - hx, y - hy);
}

// ---------------- zero + dtype detect (fused) ----------------
__global__ void k_zero(const unsigned* __restrict__ ei, int Nn) {
    long long i = (long long)blockIdx.x * blockDim.x + threadIdx.x;
    if (blockIdx.x == 0 && threadIdx.x == 0) {
        int all0 = 1;
        for (int q = 0; q < 64; q++) all0 &= (ei[2 * q + 1] == 0u);
        g_is64 = all0;
    }
    long long step = (long long)gridDim.x * blockDim.x;
    long long tot = (long long)Nn * DD;
    for (long long k = i; k < tot; k += step) g_agg[k] = 0.f;
    for (long long k = i; k < GG * DD; k += step) { g_sums[k] = 0.f; g_sq[k] = 0.f; }
    if (i < GG) g_cnt[(int)i] = 0;
}

// Build fp16 W fragments from the mma.sync B-fragment mapping:
// frag fi = ks*8+nbp, lane L:
//   b0 = W[n0  ][k0..k0+1]   (n0 = nbp*16 + (L>>2), k0 = ks*16 + 2*(L&3))
//   b1 = W[n0+8][k0..k0+1], b2 = W[n0][k0+8..], b3 = W[n0+8][k0+8..]
__global__ void k_prep_w(const float* __restrict__ We, const float* __restrict__ W1) {
    int tid = blockIdx.x * blockDim.x + threadIdx.x;   // 0..2047
    if (tid >= 2048) return;
    int fi = tid >> 5, lane = tid & 31;
    int ks = fi >> 3, nbp = fi & 7;
    int n0 = nbp * 16 + (lane >> 2);
    int k0 = ks * 16 + 2 * (lane & 3);
    {
        float2 w00 = *(const float2*)(We + n0 * DD + k0);
        float2 w10 = *(const float2*)(We + (n0 + 8) * DD + k0);
        float2 w01 = *(const float2*)(We + n0 * DD + k0 + 8);
        float2 w11 = *(const float2*)(We + (n0 + 8) * DD + k0 + 8);
        g_wfe[tid] = make_uint4(pack_h2(w00.x, w00.y), pack_h2(w10.x, w10.y),
                                pack_h2(w01.x, w01.y), pack_h2(w11.x, w11.y));
    }
    {
        float2 w00 = *(const float2*)(W1 + n0 * DD + k0);
        float2 w10 = *(const float2*)(W1 + (n0 + 8) * DD + k0);
        float2 w01 = *(const float2*)(W1 + n0 * DD + k0 + 8);
        float2 w11 = *(const float2*)(W1 + (n0 + 8) * DD + k0 + 8);
        g_wf1[tid] = make_uint4(pack_h2(w00.x, w00.y), pack_h2(w10.x, w10.y),
                                pack_h2(w01.x, w01.y), pack_h2(w11.x, w11.y));
    }
}

// ---------------- shared mma-tile machinery ----------------
// CTA = 128 threads (4 warps), tile 64 rows x 128 cols.
// Warp layout: rg = wid>>1 (32 rows), cg = wid&1 (64 cols). acc = 64 regs.
// 2-pass fp16 split: D = Ah*W + Al*W  (A exact to ~2^-22; W rounded once, ~1e-4)
#define ASTRIDE 136
#define DSTR 132
#define SM_TILE_TOTAL (64 * ASTRIDE * 4)   // 34816 B -> 4 CTAs/SM

__device__ __forceinline__ void tile_gemm_stage(char* smem, uint32_t sb,
                                                const float* __restrict__ X,
                                                const uint4* __restrict__ Wf,
                                                long long r0, long long rows, int tid) {
    int wid = tid >> 5, lane = tid & 31;
    int rg = wid >> 1, cg = wid & 1;

    // async fill of raw fp32 A tile
#pragma unroll
    for (int i = 0; i < 16; i++) {
        int idx = tid + i * 128;
        int row = idx >> 5, q = idx & 31;
        uint32_t sa = sb + (uint32_t)(row * ASTRIDE + q * 4) * 4;
        long long gr = r0 + row;
        if (gr >= rows) gr = rows - 1;   // clamp: garbage rows discarded by epilogue
        cp_async16(sa, X + gr * DD + q * 4);
    }
    cp_commit_wait();
    __syncthreads();

    const float* As = (const float*)smem;
    float acc[2][8][4];
#pragma unroll
    for (int m = 0; m < 2; m++)
#pragma unroll
        for (int i = 0; i < 8; i++)
#pragma unroll
            for (int j = 0; j < 4; j++) acc[m][i][j] = 0.f;

    int rowA = rg * 32 + (lane >> 2);
    int kcol = 2 * (lane & 3);
    const float* Ap[4];
    Ap[0] = As + rowA * ASTRIDE;
    Ap[1] = As + (rowA + 8) * ASTRIDE;
    Ap[2] = As + (rowA + 16) * ASTRIDE;
    Ap[3] = As + (rowA + 24) * ASTRIDE;

#pragma unroll 1
    for (int ks = 0; ks < 8; ks++) {
        int kb = ks * 16 + kcol;
        uint32_t ahi[2][4], alo[2][4];
#pragma unroll
        for (int m = 0; m < 2; m++) {
            float2 x0 = *(const float2*)(Ap[2 * m] + kb);
            float2 x1 = *(const float2*)(Ap[2 * m + 1] + kb);
            float2 x2 = *(const float2*)(Ap[2 * m] + kb + 8);
            float2 x3 = *(const float2*)(Ap[2 * m + 1] + kb + 8);
            ahi[m][0] = pack_h2(x0.x, x0.y); ahi[m][1] = pack_h2(x1.x, x1.y);
            ahi[m][2] = pack_h2(x2.x, x2.y); ahi[m][3] = pack_h2(x3.x, x3.y);
            alo[m][0] = pack_h2_lo(x0.x, x0.y); alo[m][1] = pack_h2_lo(x1.x, x1.y);
            alo[m][2] = pack_h2_lo(x2.x, x2.y); alo[m][3] = pack_h2_lo(x3.x, x3.y);
        }
        const uint4* wp = Wf + ks * 256 + (cg * 4) * 32 + lane;
#pragma unroll
        for (int j = 0; j < 4; j++) {
            uint4 bh = wp[j * 32];
#pragma unroll
            for (int m = 0; m < 2; m++) {
                mma_f16(acc[m][2 * j], ahi[m], bh.x, bh.z);
                mma_f16(acc[m][2 * j + 1], ahi[m], bh.y, bh.w);
                mma_f16(acc[m][2 * j], alo[m], bh.x, bh.z);
                mma_f16(acc[m][2 * j + 1], alo[m], bh.y, bh.w);
            }
        }
    }
    __syncthreads();

    // stage D (reuse tile region): warp covers rows rg*32..+31, cols cg*64..+63
    float* Ds = (float*)smem;
    {
        int cb = cg * 64 + (lane & 3) * 2;
#pragma unroll
        for (int m = 0; m < 2; m++) {
            int rbr = rg * 32 + m * 16 + (lane >> 2);
#pragma unroll
            for (int nb = 0; nb < 8; nb++) {
                *(float2*)&Ds[rbr * DSTR + cb + nb * 8] =
                    make_float2(acc[m][nb][0], acc[m][nb][1]);
                *(float2*)&Ds[(rbr + 8) * DSTR + cb + nb * 8] =
                    make_float2(acc[m][nb][2], acc[m][nb][3]);
            }
        }
    }
    __syncthreads();
}

// ---------------- node lin1 via mma ----------------
__global__ __launch_bounds__(128, 4) void k_node_mma(const float* __restrict__ X,
                                                     const float* __restrict__ bias,
                                                     int Nn) {
    extern __shared__ char smem[];
    uint32_t sb = smem_u32(smem);
    int tid = threadIdx.x;
    long long r0 = (long long)blockIdx.x * 64;
    tile_gemm_stage(smem, sb, X, g_wf1, r0, Nn, tid);

    float* Ds = (float*)smem;
    int row = tid >> 1, ch = (tid & 1) * 64;
    long long r = r0 + row;
    if (r < Nn) {
        const float* bp = bias + ch;
        float* op = g_h + r * DD + ch;
#pragma unroll
        for (int j = 0; j < 16; j++) {
            float4 dv = *(const float4*)&Ds[row * DSTR + ch + j * 4];
            float4 bb = *(const float4*)(bp + j * 4);
            *(float4*)(op + j * 4) = make_float4(dv.x + bb.x, dv.y + bb.y,
                                                 dv.z + bb.z, dv.w + bb.w);
        }
    }
}

// ---------------- edge kernel via mma + vector atomics ----------------
__global__ __launch_bounds__(128, 4) void k_edge_mma(const float* __restrict__ EA,
                                                     const float* __restrict__ bias,
                                                     const void* __restrict__ ei,
                                                     int Ee) {
    extern __shared__ char smem[];
    uint32_t sb = smem_u32(smem);
    int tid = threadIdx.x;
    long long r0 = (long long)blockIdx.x * 64;

    // hoist edge indices before tile work
    int row = tid >> 1, ch = (tid & 1) * 64;
    long long e = r0 + row;
    long long s = 0, d = 0;
    int valid = (e < Ee);
    if (valid) {
        int is64 = g_is64;
        s = ld_idx(ei, e, is64);
        d = ld_idx(ei, (long long)Ee + e, is64);
    }

    tile_gemm_stage(smem, sb, EA, g_wfe, r0, Ee, tid);

    float* Ds = (float*)smem;
    if (valid) {
        const float* hp = g_h + s * DD + ch;
        const float* bp = bias + ch;
        float4* ap = (float4*)(g_agg + d * DD + ch);
#pragma unroll
        for (int j = 0; j < 16; j++) {
            float4 dv = *(const float4*)&Ds[row * DSTR + ch + j * 4];
            float4 hv = *(const float4*)(hp + j * 4);
            float4 bb = *(const float4*)(bp + j * 4);
            float4 m;
            m.x = silu_f(dv.x + bb.x + hv.x);
            m.y = silu_f(dv.y + bb.y + hv.y);
            m.z = silu_f(dv.z + bb.z + hv.z);
            m.w = silu_f(dv.w + bb.w + hv.w);
            atomicAdd(ap + j, m);   // 128-bit RED
        }
    }
}

// ---------------- post kernels (GraphNorm, 2 passes) ----------------
__global__ void k_post1(const float* __restrict__ X, const void* __restrict__ batch,
                        const float* __restrict__ epsp, int Nn) {
    int c = threadIdx.x & 127;
    int half = threadIdx.x >> 7;
    long long n0 = (long long)blockIdx.x * 64 + half * 32;
    float ep = 1.0f + epsp[0];
    int is64 = g_is64;
    int curg = -1; float s1 = 0.f, s2 = 0.f; int cr = 0;
    for (int q = 0; q < 32; q++) {
        long long n = n0 + q;
        if (n >= Nn) break;
        long long off = n * DD + c;
        float conv = ep * g_h[off] + g_agg[off];
        float t = silu_f(conv) + X[off];
        g_t[off] = t;
        int g = (int)ld_idx(batch, n, is64);
        if (g != curg) {
            if (curg >= 0) {
                atomicAdd(&g_sums[curg * DD + c], s1);
                atomicAdd(&g_sq[curg * DD + c], s2);
                if (c == 0) atomicAdd(&g_cnt[curg], cr);
            }
            curg = g; s1 = t; s2 = t * t; cr = 1;
        } else { s1 += t; s2 += t * t; cr++; }
    }
    if (curg >= 0) {
        atomicAdd(&g_sums[curg * DD + c], s1);
        atomicAdd(&g_sq[curg * DD + c], s2);
        if (c == 0) atomicAdd(&g_cnt[curg], cr);
    }
}

__global__ void k_post3(const void* __restrict__ batch, const float* __restrict__ gw,
                        const float* __restrict__ gb, const float* __restrict__ gms,
                        float* __restrict__ out, int Nn) {
    long long i = (long long)blockIdx.x * blockDim.x + threadIdx.x;
    long long step = (long long)gridDim.x * blockDim.x;
    long long tot = (long long)Nn * DD;
    int is64 = g_is64;
    for (long long k = i; k < tot; k += step) {
        long long n = k >> 7;
        int c = (int)(k & 127);
        int g = (int)ld_idx(batch, n, is64);
        float cf = fmaxf((float)g_cnt[g], 1.f);
        float ms = gms[c];
        float mean = g_sums[g * DD + c] / cf;
        float var = g_sq[g * DD + c] / cf + mean * mean * ms * (ms - 2.0f);
        float stdv = sqrtf(var + 1e-5f);
        float o = g_t[k] - mean * ms;
        out[k] = gw[c] * o / stdv + gb[c];
    }
}

// ---------------- launcher ----------------
extern "C" void kernel_launch(void* const* d_in, const int* in_sizes, int n_in,
                              void* d_out, int out_size) {
    const float* node_h    = (const float*)d_in[0];
    const float* edge_attr = (const float*)d_in[1];
    const void*  batch     = d_in[2];
    const void*  ei        = d_in[3];
    const float* w1  = (const float*)d_in[4];
    const float* b1  = (const float*)d_in[5];
    const float* we  = (const float*)d_in[6];
    const float* be  = (const float*)d_in[7];
    const float* eps = (const float*)d_in[8];
    const float* gnw = (const float*)d_in[9];
    const float* gnb = (const float*)d_in[10];
    const float* gms = (const float*)d_in[11];

    int Nn = in_sizes[0] / DD;
    int Ee = in_sizes[1] / DD;

    cudaFuncSetAttribute(k_node_mma, cudaFuncAttributeMaxDynamicSharedMemorySize,
                         SM_TILE_TOTAL);
    cudaFuncSetAttribute(k_edge_mma, cudaFuncAttributeMaxDynamicSharedMemorySize,
                         SM_TILE_TOTAL);

    k_zero<<<1024, 256>>>((const unsigned*)ei, Nn);
    k_prep_w<<<8, 256>>>(we, w1);
    k_node_mma<<<(Nn + 63) / 64, 128, SM_TILE_TOTAL>>>(node_h, b1, Nn);
    k_edge_mma<<<(Ee + 63) / 64, 128, SM_TILE_TOTAL>>>(edge_attr, be, ei, Ee);
    k_post1<<<(Nn + 63) / 64, 256>>>(node_h, batch, eps, Nn);
    k_post3<<<2048, 256>>>(batch, gnw, gnb, gms, (float*)d_out, Nn);
}